// round 5
// baseline (speedup 1.0000x reference)
#include <cuda_runtime.h>
#include <cuda_bf16.h>
#include <math.h>

#define C 32
#define CM_SIZE (C * C)

// Scratch. Invariant: both zero at kernel_launch entry; the last block of
// hist_kernel consumes and re-zeros them each replay.
__device__ float    g_hist[CM_SIZE];
__device__ unsigned g_done = 0;

// Map float bits to unsigned such that unsigned order == float order.
__device__ __forceinline__ unsigned sortable(float f) {
    int b = __float_as_int(f);
    return (unsigned)(b ^ ((b >> 31) | 0x80000000));
}

// Lane-local argmax over 4 elements (strict > keeps first occurrence),
// packed key = (sortable & ~31) | (31 - idx): unsigned max picks larger
// value, smaller index on (mantissa-truncated) ties.
__device__ __forceinline__ unsigned local_key(float4 v, int base) {
    float best = v.x; int bi = base;
    bool c;
    c = v.y > best; best = c ? v.y : best; bi = c ? base + 1 : bi;
    c = v.z > best; best = c ? v.z : best; bi = c ? base + 2 : bi;
    c = v.w > best; best = c ? v.w : best; bi = c ? base + 3 : bi;
    return (sortable(best) & ~31u) | (unsigned)(31 - bi);
}

// Butterfly max over the 8 lanes sharing (lane >> 3); returns argmax index.
__device__ __forceinline__ int reduce8_idx(unsigned key) {
#pragma unroll
    for (int o = 1; o < 8; o <<= 1) {
        unsigned ok = __shfl_xor_sync(0xffffffffu, key, o);
        key = key > ok ? key : ok;
    }
    return 31 - (int)(key & 31u);
}

__global__ void __launch_bounds__(256) hist_kernel(
    const float* __restrict__ yt,
    const float* __restrict__ yp,
    const float* __restrict__ cm_in,
    float* __restrict__ out,
    int n_rows)
{
    __shared__ int sh[CM_SIZE];
    __shared__ unsigned s_ticket;
    for (int i = threadIdx.x; i < CM_SIZE; i += 256) sh[i] = 0;
    __syncthreads();

    const int lane = threadIdx.x & 31;
    const int gw   = (blockIdx.x * 256 + threadIdx.x) >> 5;   // global warp id
    const int nw   = (gridDim.x * 256) >> 5;                  // total warps
    const int base = (lane & 7) * 4;       // element offset within a row
    const bool is_head = (lane & 7) == 0;  // lanes 0,8,16,24

    // 16 rows per warp-iteration: 8 front-batched, fully-coalesced LDG.128.
    const int ngroups = n_rows >> 4;
    for (int g = gw; g < ngroups; g += nw) {
        const float4* at = (const float4*)(yt + (size_t)g * 16 * C);
        const float4* ap = (const float4*)(yp + (size_t)g * 16 * C);
        float4 t0 = __ldcs(at + lane);
        float4 t1 = __ldcs(at + lane + 32);
        float4 t2 = __ldcs(at + lane + 64);
        float4 t3 = __ldcs(at + lane + 96);
        float4 p0 = __ldcs(ap + lane);
        float4 p1 = __ldcs(ap + lane + 32);
        float4 p2 = __ldcs(ap + lane + 64);
        float4 p3 = __ldcs(ap + lane + 96);

        int ti0 = reduce8_idx(local_key(t0, base));
        int pi0 = reduce8_idx(local_key(p0, base));
        int ti1 = reduce8_idx(local_key(t1, base));
        int pi1 = reduce8_idx(local_key(p1, base));
        int ti2 = reduce8_idx(local_key(t2, base));
        int pi2 = reduce8_idx(local_key(p2, base));
        int ti3 = reduce8_idx(local_key(t3, base));
        int pi3 = reduce8_idx(local_key(p3, base));

        if (is_head) {   // each head lane holds one row's (t,p) per chunk
            atomicAdd(&sh[ti0 * C + pi0], 1);
            atomicAdd(&sh[ti1 * C + pi1], 1);
            atomicAdd(&sh[ti2 * C + pi2], 1);
            atomicAdd(&sh[ti3 * C + pi3], 1);
        }
    }

    // Tail (n_rows % 16 rows): scalar, global warp 0.
    if (gw == 0) {
        int tail = n_rows & 15;
        if (lane < tail) {
            size_t r = (size_t)(n_rows & ~15) + lane;
            const float* a = yt + r * C;
            const float* b = yp + r * C;
            float bt = a[0]; int ti = 0;
            float bp = b[0]; int pi = 0;
#pragma unroll
            for (int k = 1; k < C; k++) {
                if (a[k] > bt) { bt = a[k]; ti = k; }
                if (b[k] > bp) { bp = b[k]; pi = k; }
            }
            atomicAdd(&sh[ti * C + pi], 1);
        }
    }

    __syncthreads();
    for (int i = threadIdx.x; i < CM_SIZE; i += 256) {
        int v = sh[i];
        if (v) atomicAdd(&g_hist[i], (float)v);
    }

    // ── last-block finalize ──
    __threadfence();
    __syncthreads();
    if (threadIdx.x == 0) s_ticket = atomicAdd(&g_done, 1u);
    __syncthreads();
    if (s_ticket != gridDim.x - 1) return;

    // All other blocks' g_hist atomics are visible (fence before ticket).
    if (threadIdx.x < C) {
        int j = threadIdx.x;  // column index
        float colsum = 0.0f;
        float tp = 0.0f;
#pragma unroll
        for (int i = 0; i < C; i++) {
            float v = g_hist[i * C + j] + cm_in[i * C + j];
            colsum += v;
            if (i == j) tp = v;
        }
        const float EPS = 1.1920928955078125e-07f;  // FLT_EPSILON
        float prec = tp / (colsum + EPS);
#pragma unroll
        for (int o = 16; o > 0; o >>= 1)
            prec += __shfl_xor_sync(0xffffffffu, prec, o);
        if (j == 0) {
            out[0] = prec * (1.0f / C);
            g_done = 0;
        }
        __syncwarp();
        // Reset scratch for next replay; loads above already consumed.
#pragma unroll
        for (int k = 0; k < C; k++) g_hist[j * C + k] = 0.0f;
    }
}

extern "C" void kernel_launch(void* const* d_in, const int* in_sizes, int n_in,
                              void* d_out, int out_size) {
    const float* y_true = (const float*)d_in[0];
    const float* y_pred = (const float*)d_in[1];
    const float* cm_in  = (const float*)d_in[2];
    float* out = (float*)d_out;

    int n_rows = in_sizes[0] / C;

    hist_kernel<<<152 * 8, 256>>>(y_true, y_pred, cm_in, out, n_rows);
}

// round 6
// speedup vs baseline: 1.0076x; 1.0076x over previous
#include <cuda_runtime.h>
#include <cuda_bf16.h>
#include <math.h>

#define C 32
#define CM_SIZE (C * C)

// Scratch. Invariant: both zero at kernel_launch entry; the last block of
// hist_kernel consumes and re-zeros them each replay.
__device__ float    g_hist[CM_SIZE];
__device__ unsigned g_done = 0;

// Map float bits to unsigned such that unsigned order == float order.
__device__ __forceinline__ unsigned sortable(float f) {
    int b = __float_as_int(f);
    return (unsigned)(b ^ ((b >> 31) | 0x80000000));
}

// Lane-local argmax over 4 elements (strict > keeps first occurrence),
// packed key = (sortable & ~31) | (31 - idx): unsigned max picks larger
// value, smaller index on (mantissa-truncated) ties.
__device__ __forceinline__ unsigned local_key(float4 v, int base) {
    float best = v.x; int bi = base;
    bool c;
    c = v.y > best; best = c ? v.y : best; bi = c ? base + 1 : bi;
    c = v.z > best; best = c ? v.z : best; bi = c ? base + 2 : bi;
    c = v.w > best; best = c ? v.w : best; bi = c ? base + 3 : bi;
    return (sortable(best) & ~31u) | (unsigned)(31 - bi);
}

// Butterfly max over the 8 lanes sharing (lane >> 3); returns argmax index.
__device__ __forceinline__ int reduce8_idx(unsigned key) {
#pragma unroll
    for (int o = 1; o < 8; o <<= 1) {
        unsigned ok = __shfl_xor_sync(0xffffffffu, key, o);
        key = key > ok ? key : ok;
    }
    return 31 - (int)(key & 31u);
}

__global__ void __launch_bounds__(256) hist_kernel(
    const float* __restrict__ yt,
    const float* __restrict__ yp,
    const float* __restrict__ cm_in,
    float* __restrict__ out,
    int n_rows)
{
    __shared__ int sh[CM_SIZE];
    __shared__ unsigned s_ticket;
    for (int i = threadIdx.x; i < CM_SIZE; i += 256) sh[i] = 0;
    __syncthreads();

    const int lane = threadIdx.x & 31;
    const int gw   = (blockIdx.x * 256 + threadIdx.x) >> 5;   // global warp id
    const int nw   = (gridDim.x * 256) >> 5;                  // total warps
    const int base = (lane & 7) * 4;       // element offset within a row
    const bool is_head = (lane & 7) == 0;  // lanes 0,8,16,24

    // 8 rows per warp-iteration: 4 fully-coalesced 512B LDG.128 sweeps.
    const int ngroups = n_rows >> 3;
    for (int g = gw; g < ngroups; g += nw) {
        const float4* at = (const float4*)(yt + (size_t)g * 8 * C);
        const float4* ap = (const float4*)(yp + (size_t)g * 8 * C);
        float4 t0 = at[lane];
        float4 p0 = ap[lane];
        float4 t1 = at[lane + 32];
        float4 p1 = ap[lane + 32];

        int ti0 = reduce8_idx(local_key(t0, base));
        int pi0 = reduce8_idx(local_key(p0, base));
        int ti1 = reduce8_idx(local_key(t1, base));
        int pi1 = reduce8_idx(local_key(p1, base));

        if (is_head) {   // lanes 0,8,16,24 each hold one row's result
            atomicAdd(&sh[ti0 * C + pi0], 1);
            atomicAdd(&sh[ti1 * C + pi1], 1);
        }
    }

    // Tail (n_rows % 8 rows): scalar, global warp 0.
    if (gw == 0) {
        int tail = n_rows & 7;
        if (lane < tail) {
            size_t r = (size_t)(n_rows & ~7) + lane;
            const float* a = yt + r * C;
            const float* b = yp + r * C;
            float bt = a[0]; int ti = 0;
            float bp = b[0]; int pi = 0;
#pragma unroll
            for (int k = 1; k < C; k++) {
                if (a[k] > bt) { bt = a[k]; ti = k; }
                if (b[k] > bp) { bp = b[k]; pi = k; }
            }
            atomicAdd(&sh[ti * C + pi], 1);
        }
    }

    __syncthreads();
    for (int i = threadIdx.x; i < CM_SIZE; i += 256) {
        int v = sh[i];
        if (v) atomicAdd(&g_hist[i], (float)v);
    }

    // ── last-block finalize ──
    __threadfence();
    __syncthreads();
    if (threadIdx.x == 0) s_ticket = atomicAdd(&g_done, 1u);
    __syncthreads();
    if (s_ticket != gridDim.x - 1) return;

    // All other blocks' g_hist atomics are visible (fence before ticket).
    if (threadIdx.x < C) {
        int j = threadIdx.x;  // column index
        float colsum = 0.0f;
        float tp = 0.0f;
#pragma unroll
        for (int i = 0; i < C; i++) {
            float v = g_hist[i * C + j] + cm_in[i * C + j];
            colsum += v;
            if (i == j) tp = v;
        }
        const float EPS = 1.1920928955078125e-07f;  // FLT_EPSILON
        float prec = tp / (colsum + EPS);
#pragma unroll
        for (int o = 16; o > 0; o >>= 1)
            prec += __shfl_xor_sync(0xffffffffu, prec, o);
        if (j == 0) {
            out[0] = prec * (1.0f / C);
            g_done = 0;
        }
        __syncwarp();
        // Reset scratch for next replay; loads above already consumed.
#pragma unroll
        for (int k = 0; k < C; k++) g_hist[j * C + k] = 0.0f;
    }
}

extern "C" void kernel_launch(void* const* d_in, const int* in_sizes, int n_in,
                              void* d_out, int out_size) {
    const float* y_true = (const float*)d_in[0];
    const float* y_pred = (const float*)d_in[1];
    const float* cm_in  = (const float*)d_in[2];
    float* out = (float*)d_out;

    int n_rows = in_sizes[0] / C;

    hist_kernel<<<152 * 8, 256>>>(y_true, y_pred, cm_in, out, n_rows);
}

// round 7
// speedup vs baseline: 1.0263x; 1.0185x over previous
#include <cuda_runtime.h>
#include <cuda_bf16.h>
#include <math.h>

#define C 32
#define CM_SIZE (C * C)

// Scratch confusion-matrix accumulator. Invariant: zero at kernel_launch entry.
// hist_kernel accumulates; finalize_kernel reads it and resets it to zero.
__device__ float g_hist[CM_SIZE];

// Map float bits to unsigned such that unsigned order == float order.
__device__ __forceinline__ unsigned sortable(float f) {
    int b = __float_as_int(f);
    return (unsigned)(b ^ ((b >> 31) | 0x80000000));
}

// Lane-local argmax over 4 elements (strict > keeps first occurrence),
// packed as key = (sortable_value & ~31) | (31 - idx) so that unsigned max
// picks the larger value, and the SMALLER index on (truncated) ties.
__device__ __forceinline__ unsigned local_key(float4 v, int base) {
    float best = v.x; int bi = base;
    bool c;
    c = v.y > best; best = c ? v.y : best; bi = c ? base + 1 : bi;
    c = v.z > best; best = c ? v.z : best; bi = c ? base + 2 : bi;
    c = v.w > best; best = c ? v.w : best; bi = c ? base + 3 : bi;
    return (sortable(best) & ~31u) | (unsigned)(31 - bi);
}

// Butterfly max over the 8 lanes sharing (lane >> 3); returns argmax index.
__device__ __forceinline__ int reduce8_idx(unsigned key) {
#pragma unroll
    for (int o = 1; o < 8; o <<= 1) {
        unsigned ok = __shfl_xor_sync(0xffffffffu, key, o);
        key = key > ok ? key : ok;
    }
    return 31 - (int)(key & 31u);
}

__global__ void __launch_bounds__(256) hist_kernel(
    const float* __restrict__ yt,
    const float* __restrict__ yp,
    int n_rows)
{
    __shared__ int sh[CM_SIZE];
    for (int i = threadIdx.x; i < CM_SIZE; i += 256) sh[i] = 0;
    __syncthreads();

    const int lane = threadIdx.x & 31;
    const int gw   = (blockIdx.x * 256 + threadIdx.x) >> 5;   // global warp id
    const int nw   = (gridDim.x * 256) >> 5;                  // total warps
    const int base = (lane & 7) * 4;   // element offset within row
    const bool is_head = (lane & 7) == 0;

    // 8 rows per warp-iteration: 4 fully-coalesced 512B LDG.128 sweeps.
    const int ngroups = n_rows >> 3;
    for (int g = gw; g < ngroups; g += nw) {
        const float4* at = (const float4*)(yt + (size_t)g * 8 * C);
        const float4* ap = (const float4*)(yp + (size_t)g * 8 * C);
        float4 t0 = at[lane];
        float4 p0 = ap[lane];
        float4 t1 = at[lane + 32];
        float4 p1 = ap[lane + 32];

        unsigned kt0 = local_key(t0, base);
        unsigned kp0 = local_key(p0, base);
        unsigned kt1 = local_key(t1, base);
        unsigned kp1 = local_key(p1, base);

        int ti0 = reduce8_idx(kt0);
        int pi0 = reduce8_idx(kp0);
        int ti1 = reduce8_idx(kt1);
        int pi1 = reduce8_idx(kp1);

        if (is_head) {   // lanes 0,8,16,24 each hold one row's result
            atomicAdd(&sh[ti0 * C + pi0], 1);
            atomicAdd(&sh[ti1 * C + pi1], 1);
        }
    }

    // Tail (n_rows % 8 rows): scalar, handled by global warp 0.
    if (gw == 0) {
        int tail = n_rows & 7;
        if (lane < tail) {
            size_t r = (size_t)(n_rows & ~7) + lane;
            const float* a = yt + r * C;
            const float* b = yp + r * C;
            float bt = a[0]; int ti = 0;
            float bp = b[0]; int pi = 0;
#pragma unroll
            for (int k = 1; k < C; k++) {
                if (a[k] > bt) { bt = a[k]; ti = k; }
                if (b[k] > bp) { bp = b[k]; pi = k; }
            }
            atomicAdd(&sh[ti * C + pi], 1);
        }
    }

    __syncthreads();
    for (int i = threadIdx.x; i < CM_SIZE; i += 256) {
        int v = sh[i];
        if (v) atomicAdd(&g_hist[i], (float)v);
    }
}

__global__ void finalize_kernel(const float* __restrict__ cm_in, float* __restrict__ out) {
    // PDL: block may be scheduled while hist_kernel still runs; wait until the
    // full upstream grid has completed (and its memory is visible) before
    // reading g_hist.
    cudaGridDependencySynchronize();

    int j = threadIdx.x;  // column index, single warp
    float colsum = 0.0f;
    float tp = 0.0f;
#pragma unroll
    for (int i = 0; i < C; i++) {
        float v = g_hist[i * C + j] + cm_in[i * C + j];
        colsum += v;
        if (i == j) tp = v;
    }
    const float EPS = 1.1920928955078125e-07f;  // FLT_EPSILON
    float prec = tp / (colsum + EPS);
#pragma unroll
    for (int o = 16; o > 0; o >>= 1)
        prec += __shfl_xor_sync(0xffffffffu, prec, o);
    if (j == 0) out[0] = prec * (1.0f / C);
    __syncwarp();
    // Reset scratch for the next graph replay. Safe: every lane's loads were
    // consumed by the shfl reduction above, which precedes these stores in
    // warp-synchronous program order.
#pragma unroll
    for (int k = 0; k < C; k++) g_hist[j * C + k] = 0.0f;
}

extern "C" void kernel_launch(void* const* d_in, const int* in_sizes, int n_in,
                              void* d_out, int out_size) {
    const float* y_true = (const float*)d_in[0];
    const float* y_pred = (const float*)d_in[1];
    const float* cm_in  = (const float*)d_in[2];
    float* out = (float*)d_out;

    int n_rows = in_sizes[0] / C;

    hist_kernel<<<152 * 8, 256>>>(y_true, y_pred, n_rows);

    // Launch finalize with Programmatic Dependent Launch: its launch overhead
    // overlaps hist_kernel's tail; cudaGridDependencySynchronize() inside the
    // kernel provides the ordering.
    cudaLaunchConfig_t cfg = {};
    cfg.gridDim  = dim3(1, 1, 1);
    cfg.blockDim = dim3(C, 1, 1);
    cfg.dynamicSmemBytes = 0;
    cfg.stream = 0;  // legacy default stream (same stream <<<>>> uses)
    cudaLaunchAttribute attr[1];
    attr[0].id = cudaLaunchAttributeProgrammaticStreamSerialization;
    attr[0].val.programmaticStreamSerializationAllowed = 1;
    cfg.attrs = attr;
    cfg.numAttrs = 1;
    cudaLaunchKernelEx(&cfg, finalize_kernel, cm_in, out);
}

// round 8
// speedup vs baseline: 1.0508x; 1.0239x over previous
#include <cuda_runtime.h>
#include <cuda_bf16.h>
#include <math.h>

#define C 32
#define CM_SIZE (C * C)

// Scratch confusion-matrix accumulator. Invariant: zero at kernel_launch entry.
// hist_kernel accumulates; finalize_kernel reads it and resets it to zero.
__device__ float g_hist[CM_SIZE];

struct V8 { float4 a, b; };

// 256-bit global load (Blackwell LDG.E.256). p must be 32B-aligned.
__device__ __forceinline__ V8 ldg256(const float* p) {
    V8 r;
    asm volatile("ld.global.v8.f32 {%0,%1,%2,%3,%4,%5,%6,%7}, [%8];"
        : "=f"(r.a.x), "=f"(r.a.y), "=f"(r.a.z), "=f"(r.a.w),
          "=f"(r.b.x), "=f"(r.b.y), "=f"(r.b.z), "=f"(r.b.w)
        : "l"(p));
    return r;
}

// Map float bits to unsigned such that unsigned order == float order.
__device__ __forceinline__ unsigned sortable(float f) {
    int b = __float_as_int(f);
    return (unsigned)(b ^ ((b >> 31) | 0x80000000));
}

// Lane-local argmax over 8 contiguous elements (strict > keeps first max),
// packed key = (sortable & ~31) | (31 - idx): unsigned max picks larger
// value, smaller index on (mantissa-truncated) ties.
__device__ __forceinline__ unsigned local_key8(const V8& v, int base) {
    float best = v.a.x; int bi = base;
    bool c;
    c = v.a.y > best; best = c ? v.a.y : best; bi = c ? base + 1 : bi;
    c = v.a.z > best; best = c ? v.a.z : best; bi = c ? base + 2 : bi;
    c = v.a.w > best; best = c ? v.a.w : best; bi = c ? base + 3 : bi;
    c = v.b.x > best; best = c ? v.b.x : best; bi = c ? base + 4 : bi;
    c = v.b.y > best; best = c ? v.b.y : best; bi = c ? base + 5 : bi;
    c = v.b.z > best; best = c ? v.b.z : best; bi = c ? base + 6 : bi;
    c = v.b.w > best; best = c ? v.b.w : best; bi = c ? base + 7 : bi;
    return (sortable(best) & ~31u) | (unsigned)(31 - bi);
}

// Butterfly max over the 4 lanes sharing (lane >> 2); returns argmax index.
__device__ __forceinline__ int reduce4_idx(unsigned key) {
#pragma unroll
    for (int o = 1; o < 4; o <<= 1) {
        unsigned ok = __shfl_xor_sync(0xffffffffu, key, o);
        key = key > ok ? key : ok;
    }
    return 31 - (int)(key & 31u);
}

__global__ void __launch_bounds__(256, 6) hist_kernel(
    const float* __restrict__ yt,
    const float* __restrict__ yp,
    int n_rows)
{
    __shared__ int sh[CM_SIZE];
    for (int i = threadIdx.x; i < CM_SIZE; i += 256) sh[i] = 0;
    __syncthreads();

    const int lane = threadIdx.x & 31;
    const int gw   = (blockIdx.x * 256 + threadIdx.x) >> 5;   // global warp id
    const int nw   = (gridDim.x * 256) >> 5;                  // total warps
    const int base = (lane & 3) * 8;       // element offset within a row
    const bool is_head = (lane & 3) == 0;  // one head lane per row-quad

    // 16 rows per warp-iteration via 4 front-batched LDG.256:
    // lane covers elements [lane*8, lane*8+8) of a 256-element (8-row) span,
    // i.e. 8 contiguous elements of row (lane >> 2).
    const int ngroups = n_rows >> 4;
    for (int g = gw; g < ngroups; g += nw) {
        const float* at = yt + (size_t)g * 16 * C;
        const float* ap = yp + (size_t)g * 16 * C;
        V8 t0 = ldg256(at + lane * 8);          // rows 16g+0  .. +7
        V8 t1 = ldg256(at + 256 + lane * 8);    // rows 16g+8  .. +15
        V8 p0 = ldg256(ap + lane * 8);
        V8 p1 = ldg256(ap + 256 + lane * 8);

        int ti0 = reduce4_idx(local_key8(t0, base));
        int pi0 = reduce4_idx(local_key8(p0, base));
        int ti1 = reduce4_idx(local_key8(t1, base));
        int pi1 = reduce4_idx(local_key8(p1, base));

        if (is_head) {   // lanes 0,4,...,28: one row per quad, two row-banks
            atomicAdd(&sh[ti0 * C + pi0], 1);
            atomicAdd(&sh[ti1 * C + pi1], 1);
        }
    }

    // Tail (n_rows % 16 rows): scalar, handled by global warp 0.
    if (gw == 0) {
        int tail = n_rows & 15;
        if (lane < tail) {
            size_t r = (size_t)(n_rows & ~15) + lane;
            const float* a = yt + r * C;
            const float* b = yp + r * C;
            float bt = a[0]; int ti = 0;
            float bp = b[0]; int pi = 0;
#pragma unroll
            for (int k = 1; k < C; k++) {
                if (a[k] > bt) { bt = a[k]; ti = k; }
                if (b[k] > bp) { bp = b[k]; pi = k; }
            }
            atomicAdd(&sh[ti * C + pi], 1);
        }
    }

    __syncthreads();
    for (int i = threadIdx.x; i < CM_SIZE; i += 256) {
        int v = sh[i];
        if (v) atomicAdd(&g_hist[i], (float)v);
    }
}

__global__ void finalize_kernel(const float* __restrict__ cm_in, float* __restrict__ out) {
    int j = threadIdx.x;  // column index, single warp
    float colsum = 0.0f;
    float tp = 0.0f;
#pragma unroll
    for (int i = 0; i < C; i++) {
        float v = g_hist[i * C + j] + cm_in[i * C + j];
        colsum += v;
        if (i == j) tp = v;
    }
    const float EPS = 1.1920928955078125e-07f;  // FLT_EPSILON
    float prec = tp / (colsum + EPS);
#pragma unroll
    for (int o = 16; o > 0; o >>= 1)
        prec += __shfl_xor_sync(0xffffffffu, prec, o);
    if (j == 0) out[0] = prec * (1.0f / C);
    __syncwarp();
    // Reset scratch for the next graph replay. Safe: every lane's loads were
    // consumed by the shfl reduction above, which precedes these stores in
    // warp-synchronous program order.
#pragma unroll
    for (int k = 0; k < C; k++) g_hist[j * C + k] = 0.0f;
}

extern "C" void kernel_launch(void* const* d_in, const int* in_sizes, int n_in,
                              void* d_out, int out_size) {
    const float* y_true = (const float*)d_in[0];
    const float* y_pred = (const float*)d_in[1];
    const float* cm_in  = (const float*)d_in[2];
    float* out = (float*)d_out;

    int n_rows = in_sizes[0] / C;

    // 152 SMs * 6 blocks (regs-limited occupancy target) — exactly one wave.
    hist_kernel<<<152 * 6, 256>>>(y_true, y_pred, n_rows);
    finalize_kernel<<<1, C>>>(cm_in, out);
}

// round 9
// speedup vs baseline: 1.0715x; 1.0197x over previous
#include <cuda_runtime.h>
#include <cuda_bf16.h>
#include <math.h>

#define C 32
#define CM_SIZE (C * C)
#define NT 512   // threads per block

// Scratch confusion-matrix accumulator. Invariant: zero at kernel_launch entry.
// hist_kernel accumulates; finalize_kernel reads it and resets it to zero.
__device__ float g_hist[CM_SIZE];

// Map float bits to unsigned such that unsigned order == float order.
__device__ __forceinline__ unsigned sortable(float f) {
    int b = __float_as_int(f);
    return (unsigned)(b ^ ((b >> 31) | 0x80000000));
}

// Lane-local argmax over 4 elements (strict > keeps first occurrence),
// packed as key = (sortable_value & ~31) | (31 - idx) so that unsigned max
// picks the larger value, and the SMALLER index on (truncated) ties.
__device__ __forceinline__ unsigned local_key(float4 v, int base) {
    float best = v.x; int bi = base;
    bool c;
    c = v.y > best; best = c ? v.y : best; bi = c ? base + 1 : bi;
    c = v.z > best; best = c ? v.z : best; bi = c ? base + 2 : bi;
    c = v.w > best; best = c ? v.w : best; bi = c ? base + 3 : bi;
    return (sortable(best) & ~31u) | (unsigned)(31 - bi);
}

// Butterfly max over the 8 lanes sharing (lane >> 3); returns argmax index.
__device__ __forceinline__ int reduce8_idx(unsigned key) {
#pragma unroll
    for (int o = 1; o < 8; o <<= 1) {
        unsigned ok = __shfl_xor_sync(0xffffffffu, key, o);
        key = key > ok ? key : ok;
    }
    return 31 - (int)(key & 31u);
}

__global__ void __launch_bounds__(NT, 4) hist_kernel(
    const float* __restrict__ yt,
    const float* __restrict__ yp,
    int n_rows)
{
    __shared__ int sh[CM_SIZE];
    for (int i = threadIdx.x; i < CM_SIZE; i += NT) sh[i] = 0;
    __syncthreads();

    const int lane = threadIdx.x & 31;
    const int gw   = (blockIdx.x * NT + threadIdx.x) >> 5;    // global warp id
    const int nw   = (gridDim.x * NT) >> 5;                   // total warps
    const int base = (lane & 7) * 4;   // element offset within row
    const bool is_head = (lane & 7) == 0;

    // 8 rows per warp-iteration: 4 fully-coalesced 512B LDG.128 sweeps.
    const int ngroups = n_rows >> 3;
    for (int g = gw; g < ngroups; g += nw) {
        const float4* at = (const float4*)(yt + (size_t)g * 8 * C);
        const float4* ap = (const float4*)(yp + (size_t)g * 8 * C);
        float4 t0 = at[lane];
        float4 p0 = ap[lane];
        float4 t1 = at[lane + 32];
        float4 p1 = ap[lane + 32];

        unsigned kt0 = local_key(t0, base);
        unsigned kp0 = local_key(p0, base);
        unsigned kt1 = local_key(t1, base);
        unsigned kp1 = local_key(p1, base);

        int ti0 = reduce8_idx(kt0);
        int pi0 = reduce8_idx(kp0);
        int ti1 = reduce8_idx(kt1);
        int pi1 = reduce8_idx(kp1);

        if (is_head) {   // lanes 0,8,16,24 each hold one row's result
            atomicAdd(&sh[ti0 * C + pi0], 1);
            atomicAdd(&sh[ti1 * C + pi1], 1);
        }
    }

    // Tail (n_rows % 8 rows): scalar, handled by global warp 0.
    if (gw == 0) {
        int tail = n_rows & 7;
        if (lane < tail) {
            size_t r = (size_t)(n_rows & ~7) + lane;
            const float* a = yt + r * C;
            const float* b = yp + r * C;
            float bt = a[0]; int ti = 0;
            float bp = b[0]; int pi = 0;
#pragma unroll
            for (int k = 1; k < C; k++) {
                if (a[k] > bt) { bt = a[k]; ti = k; }
                if (b[k] > bp) { bp = b[k]; pi = k; }
            }
            atomicAdd(&sh[ti * C + pi], 1);
        }
    }

    __syncthreads();
    // Staggered flush: block b starts at a different histogram offset so
    // concurrent blocks hit different addresses / LTS slices instead of
    // convoying per-address at the L2 atomic ALU.
    {
        int off = (blockIdx.x * 131) & (CM_SIZE - 1);
        for (int i = threadIdx.x; i < CM_SIZE; i += NT) {
            int idx = (i + off) & (CM_SIZE - 1);
            int v = sh[idx];
            if (v) atomicAdd(&g_hist[idx], (float)v);
        }
    }
}

__global__ void finalize_kernel(const float* __restrict__ cm_in, float* __restrict__ out) {
    int j = threadIdx.x;  // column index, single warp
    float colsum = 0.0f;
    float tp = 0.0f;
#pragma unroll
    for (int i = 0; i < C; i++) {
        float v = g_hist[i * C + j] + cm_in[i * C + j];
        colsum += v;
        if (i == j) tp = v;
    }
    const float EPS = 1.1920928955078125e-07f;  // FLT_EPSILON
    float prec = tp / (colsum + EPS);
#pragma unroll
    for (int o = 16; o > 0; o >>= 1)
        prec += __shfl_xor_sync(0xffffffffu, prec, o);
    if (j == 0) out[0] = prec * (1.0f / C);
    __syncwarp();
    // Reset scratch for the next graph replay. Safe: every lane's loads were
    // consumed by the shfl reduction above, which precedes these stores in
    // warp-synchronous program order.
#pragma unroll
    for (int k = 0; k < C; k++) g_hist[j * C + k] = 0.0f;
}

extern "C" void kernel_launch(void* const* d_in, const int* in_sizes, int n_in,
                              void* d_out, int out_size) {
    const float* y_true = (const float*)d_in[0];
    const float* y_pred = (const float*)d_in[1];
    const float* cm_in  = (const float*)d_in[2];
    float* out = (float*)d_out;

    int n_rows = in_sizes[0] / C;

    // 152 SMs * 4 blocks of 512 threads: same 2048 threads/SM as before, but
    // half the blocks -> half the end-of-kernel global atomic flush traffic.
    hist_kernel<<<152 * 4, NT>>>(y_true, y_pred, n_rows);
    finalize_kernel<<<1, C>>>(cm_in, out);
}

// round 10
// speedup vs baseline: 1.0823x; 1.0101x over previous
#include <cuda_runtime.h>
#include <cuda_bf16.h>
#include <math.h>

#define C 32
#define CM_SIZE (C * C)
#define NT 1024  // threads per block

// Scratch confusion-matrix accumulator. Invariant: zero at kernel_launch entry.
// hist_kernel accumulates; finalize_kernel reads it and resets it to zero.
__device__ float g_hist[CM_SIZE];

// Map float bits to unsigned such that unsigned order == float order.
__device__ __forceinline__ unsigned sortable(float f) {
    int b = __float_as_int(f);
    return (unsigned)(b ^ ((b >> 31) | 0x80000000));
}

// Lane-local argmax over 4 elements (strict > keeps first occurrence),
// packed as key = (sortable_value & ~31) | (31 - idx) so that unsigned max
// picks the larger value, and the SMALLER index on (truncated) ties.
__device__ __forceinline__ unsigned local_key(float4 v, int base) {
    float best = v.x; int bi = base;
    bool c;
    c = v.y > best; best = c ? v.y : best; bi = c ? base + 1 : bi;
    c = v.z > best; best = c ? v.z : best; bi = c ? base + 2 : bi;
    c = v.w > best; best = c ? v.w : best; bi = c ? base + 3 : bi;
    return (sortable(best) & ~31u) | (unsigned)(31 - bi);
}

// Butterfly max over the 8 lanes sharing (lane >> 3); returns argmax index.
__device__ __forceinline__ int reduce8_idx(unsigned key) {
#pragma unroll
    for (int o = 1; o < 8; o <<= 1) {
        unsigned ok = __shfl_xor_sync(0xffffffffu, key, o);
        key = key > ok ? key : ok;
    }
    return 31 - (int)(key & 31u);
}

__global__ void __launch_bounds__(NT, 2) hist_kernel(
    const float* __restrict__ yt,
    const float* __restrict__ yp,
    int n_rows)
{
    __shared__ int sh[CM_SIZE];
    for (int i = threadIdx.x; i < CM_SIZE; i += NT) sh[i] = 0;
    __syncthreads();

    const int lane = threadIdx.x & 31;
    const int gw   = (blockIdx.x * NT + threadIdx.x) >> 5;    // global warp id
    const int nw   = (gridDim.x * NT) >> 5;                   // total warps
    const int base = (lane & 7) * 4;   // element offset within row
    const bool is_head = (lane & 7) == 0;

    // 8 rows per warp-iteration: 4 fully-coalesced 512B LDG.128 sweeps.
    const int ngroups = n_rows >> 3;
    for (int g = gw; g < ngroups; g += nw) {
        const float4* at = (const float4*)(yt + (size_t)g * 8 * C);
        const float4* ap = (const float4*)(yp + (size_t)g * 8 * C);
        float4 t0 = at[lane];
        float4 p0 = ap[lane];
        float4 t1 = at[lane + 32];
        float4 p1 = ap[lane + 32];

        unsigned kt0 = local_key(t0, base);
        unsigned kp0 = local_key(p0, base);
        unsigned kt1 = local_key(t1, base);
        unsigned kp1 = local_key(p1, base);

        int ti0 = reduce8_idx(kt0);
        int pi0 = reduce8_idx(kp0);
        int ti1 = reduce8_idx(kt1);
        int pi1 = reduce8_idx(kp1);

        if (is_head) {   // lanes 0,8,16,24 each hold one row's result
            atomicAdd(&sh[ti0 * C + pi0], 1);
            atomicAdd(&sh[ti1 * C + pi1], 1);
        }
    }

    // Tail (n_rows % 8 rows): scalar, handled by global warp 0.
    if (gw == 0) {
        int tail = n_rows & 7;
        if (lane < tail) {
            size_t r = (size_t)(n_rows & ~7) + lane;
            const float* a = yt + r * C;
            const float* b = yp + r * C;
            float bt = a[0]; int ti = 0;
            float bp = b[0]; int pi = 0;
#pragma unroll
            for (int k = 1; k < C; k++) {
                if (a[k] > bt) { bt = a[k]; ti = k; }
                if (b[k] > bp) { bp = b[k]; pi = k; }
            }
            atomicAdd(&sh[ti * C + pi], 1);
        }
    }

    __syncthreads();
    // Staggered flush: block b starts at a different histogram offset so
    // concurrent blocks hit different addresses / LTS slices instead of
    // convoying per-address at the L2 atomic ALU.
    {
        int off = (blockIdx.x * 131) & (CM_SIZE - 1);
        for (int i = threadIdx.x; i < CM_SIZE; i += NT) {
            int idx = (i + off) & (CM_SIZE - 1);
            int v = sh[idx];
            if (v) atomicAdd(&g_hist[idx], (float)v);
        }
    }
}

__global__ void finalize_kernel(const float* __restrict__ cm_in, float* __restrict__ out) {
    int j = threadIdx.x;  // column index, single warp
    float colsum = 0.0f;
    float tp = 0.0f;
#pragma unroll
    for (int i = 0; i < C; i++) {
        float v = g_hist[i * C + j] + cm_in[i * C + j];
        colsum += v;
        if (i == j) tp = v;
    }
    const float EPS = 1.1920928955078125e-07f;  // FLT_EPSILON
    float prec = tp / (colsum + EPS);
#pragma unroll
    for (int o = 16; o > 0; o >>= 1)
        prec += __shfl_xor_sync(0xffffffffu, prec, o);
    if (j == 0) out[0] = prec * (1.0f / C);
    __syncwarp();
    // Reset scratch for the next graph replay. Safe: every lane's loads were
    // consumed by the shfl reduction above, which precedes these stores in
    // warp-synchronous program order.
#pragma unroll
    for (int k = 0; k < C; k++) g_hist[j * C + k] = 0.0f;
}

extern "C" void kernel_launch(void* const* d_in, const int* in_sizes, int n_in,
                              void* d_out, int out_size) {
    const float* y_true = (const float*)d_in[0];
    const float* y_pred = (const float*)d_in[1];
    const float* cm_in  = (const float*)d_in[2];
    float* out = (float*)d_out;

    int n_rows = in_sizes[0] / C;

    // 152 SMs * 2 blocks of 1024 threads: same 2048 threads/SM, but half the
    // blocks of R8 -> half the end-of-kernel global atomic flush traffic.
    hist_kernel<<<152 * 2, NT>>>(y_true, y_pred, n_rows);
    finalize_kernel<<<1, C>>>(cm_in, out);
}